// round 9
// baseline (speedup 1.0000x reference)
#include <cuda_runtime.h>
#include <cuda_bf16.h>
#include <stdint.h>

// Problem constants
#define DIM   256
#define NC    1024
#define NPTS  65536
#define D4    (DIM/4)

// ---- filter kernel geometry ----
#define ROWS_CTA 64
#define NCT      8          // code tiles of 128
#define KC       64
#define THR      256        // 8 warps: wy=wid>>2 (M: 32 rows), wx=wid&3 (N: 32 codes)
#define NSTAGE   32         // NCT * (DIM/KC)
#define TAU      1.25e-4f

// filter smem offsets
#define SM_WSQ   0                     // 4 KB
#define SM_RED   4096                  // 4 KB: rv1,ri1,rv2,ri2 [64][4]
#define SM_A     8192                  // 2 splits x 4 kc x 64 r x 128 B = 64 KB
#define SM_B     (SM_A + 65536)        // 4 bufs x 2 splits x 128 r x 128 B = 128 KB
#define SM_TOTAL (SM_B + 131072)       // 204800 B

// ---- resolver geometry (proven-exact fp32 rescan, indirect rows) ----
#define RBM   64
#define RBN   128
#define RKC4  32
#define RTM   8
#define RTN   4
#define RCHALF 512
#define RNTILE (RCHALF/RBN)
#define RSM_TOTAL (65536 + 65536 + 256)

// Scratch (static device globals; no allocation)
__device__ int   g_idx[NPTS];
__device__ float g_wsq[NC];
__device__ float g_zsq[NPTS];
__device__ int   g_ambig_n;
__device__ int   g_ambig[NPTS];
__device__ float g_best2[2][NPTS];
__device__ int   g_bidx2[2][NPTS];
__device__ __align__(16) unsigned short g_zh[NPTS * DIM];
__device__ __align__(16) unsigned short g_zm[NPTS * DIM];
__device__ __align__(16) unsigned short g_wh[NC * DIM];
__device__ __align__(16) unsigned short g_wm[NC * DIM];

// ---- PTX helpers (baseline ops only; no arch-'a' features) -----------------
static __device__ __forceinline__ uint32_t smem_u32(const void* p) {
    uint32_t a;
    asm("{ .reg .u64 t; cvta.to.shared.u64 t, %1; cvt.u32.u64 %0, t; }"
        : "=r"(a) : "l"(p));
    return a;
}
#define CP16(dst, src) \
    asm volatile("cp.async.cg.shared.global [%0], [%1], 16;" :: "r"(dst), "l"(src))
#define LDSM4(r, addr) \
    asm volatile("ldmatrix.sync.aligned.m8n8.x4.shared.b16 {%0,%1,%2,%3}, [%4];" \
                 : "=r"((r)[0]), "=r"((r)[1]), "=r"((r)[2]), "=r"((r)[3]) : "r"(addr))
#define MMA16816(d, a, b) \
    asm volatile("mma.sync.aligned.m16n8k16.row.col.f32.bf16.bf16.f32 " \
                 "{%0,%1,%2,%3}, {%4,%5,%6,%7}, {%8,%9}, {%0,%1,%2,%3};" \
                 : "+f"((d)[0]), "+f"((d)[1]), "+f"((d)[2]), "+f"((d)[3]) \
                 : "r"((a)[0]), "r"((a)[1]), "r"((a)[2]), "r"((a)[3]), \
                   "r"((b)[0]), "r"((b)[1]))
static __device__ __forceinline__ void fma2(unsigned long long& d,
                                            unsigned long long a,
                                            unsigned long long b) {
    asm("fma.rn.f32x2 %0, %1, %2, %0;" : "+l"(d) : "l"(a), "l"(b));
}
static __device__ __forceinline__ void unpack2(unsigned long long v,
                                               float& lo, float& hi) {
    asm("mov.b64 {%0, %1}, %2;" : "=f"(lo), "=f"(hi) : "l"(v));
}

// 2-way Dekker split: x = h + m + r (residuals exact)
static __device__ __forceinline__ void split2(float x, unsigned short& h,
                                              unsigned short& m) {
    __nv_bfloat16 bh = __float2bfloat16_rn(x);
    float r1 = x - __bfloat162float(bh);   // exact
    __nv_bfloat16 bm = __float2bfloat16_rn(r1);
    h = __bfloat16_as_ushort(bh);
    m = __bfloat16_as_ushort(bm);
}

// ---------------------------------------------------------------------------
// [0] reset worklist counter
// ---------------------------------------------------------------------------
__global__ void reset_kernel() { g_ambig_n = 0; }

// ---------------------------------------------------------------------------
// [1] split w -> (wh, wm) + |w|^2
// ---------------------------------------------------------------------------
__global__ void split_w_kernel(const float* __restrict__ w) {
    int row  = (blockIdx.x * blockDim.x + threadIdx.x) >> 5;
    int lane = threadIdx.x & 31;
    if (row >= NC) return;
    const float4* src = reinterpret_cast<const float4*>(w + (size_t)row * DIM);
    float s = 0.f;
#pragma unroll
    for (int i = 0; i < 2; i++) {
        float4 v = src[lane + 32 * i];
        float x[4] = {v.x, v.y, v.z, v.w};
        unsigned short h[4], m[4];
#pragma unroll
        for (int j = 0; j < 4; j++) { split2(x[j], h[j], m[j]); s += x[j] * x[j]; }
        size_t o = (size_t)row * D4 + lane + 32 * i;
        reinterpret_cast<ushort4*>(g_wh)[o] = make_ushort4(h[0], h[1], h[2], h[3]);
        reinterpret_cast<ushort4*>(g_wm)[o] = make_ushort4(m[0], m[1], m[2], m[3]);
    }
#pragma unroll
    for (int t = 16; t >= 1; t >>= 1) s += __shfl_xor_sync(0xffffffffu, s, t);
    if (lane == 0) g_wsq[row] = s;
}

// ---------------------------------------------------------------------------
// [2] split z -> (zh, zm) + |z|^2 (fused)
// ---------------------------------------------------------------------------
__global__ void split_z_kernel(const float* __restrict__ z) {
    int row  = (blockIdx.x * blockDim.x + threadIdx.x) >> 5;
    int lane = threadIdx.x & 31;
    if (row >= NPTS) return;
    const float4* src = reinterpret_cast<const float4*>(z + (size_t)row * DIM);
    float s = 0.f;
#pragma unroll
    for (int i = 0; i < 2; i++) {
        float4 v = src[lane + 32 * i];
        float x[4] = {v.x, v.y, v.z, v.w};
        unsigned short h[4], m[4];
#pragma unroll
        for (int j = 0; j < 4; j++) { split2(x[j], h[j], m[j]); s += x[j] * x[j]; }
        size_t o = (size_t)row * D4 + lane + 32 * i;
        reinterpret_cast<ushort4*>(g_zh)[o] = make_ushort4(h[0], h[1], h[2], h[3]);
        reinterpret_cast<ushort4*>(g_zm)[o] = make_ushort4(m[0], m[1], m[2], m[3]);
    }
#pragma unroll
    for (int t = 16; t >= 1; t >>= 1) s += __shfl_xor_sync(0xffffffffu, s, t);
    if (lane == 0) g_zsq[row] = s;
}

// ---------------------------------------------------------------------------
// B chunk stage into ring buffer (it mod 4): 2 splits x 128 codes x 64 k
// ---------------------------------------------------------------------------
static __device__ __forceinline__ void stage_B_chunk(uint32_t sb, int tid, int it) {
    const unsigned short* const ws[2] = {g_wh, g_wm};
    const int ct = it >> 2, kc = it & 3, buf = it & 3;
#pragma unroll
    for (int i = tid; i < 2048; i += THR) {
        int s   = i >> 10;
        int rem = i & 1023;
        int r = rem >> 3, q = rem & 7;
        const unsigned short* src = ws[s] + ((size_t)(ct * 128 + r) * DIM + kc * KC + q * 8);
        uint32_t off = (uint32_t)(r * 128 + ((q * 16) ^ ((r & 7) << 4)));
        CP16(sb + SM_B + buf * 32768 + s * 16384 + off, src);
    }
}

// lex insert of candidate (v,i) into best-2
static __device__ __forceinline__ void ins2(float v, int i, float& b1v, int& b1i,
                                            float& b2v, int& b2i) {
    if (v < b1v || (v == b1v && i < b1i)) { b2v = b1v; b2i = b1i; b1v = v; b1i = i; }
    else if (v < b2v || (v == b2v && i < b2i)) { b2v = v; b2i = i; }
}

// load one k16 step's fragments into frag set SET (compile-time index)
#define LOADFRAGS(SET, ABASE, BBASE, K16) do {                                   \
    uint32_t ak_ = ((uint32_t)((K16) * 32) + akh) ^ xl;                          \
    uint32_t bk_ = ((uint32_t)((K16) * 32) + bkh) ^ xl;                          \
    _Pragma("unroll")                                                            \
    for (int s_ = 0; s_ < 2; s_++) {                                             \
        _Pragma("unroll")                                                        \
        for (int mt_ = 0; mt_ < 2; mt_++)                                        \
            LDSM4(af[SET][s_][mt_], (ABASE) + s_ * 32768 + mt_ * 2048 + ak_);    \
        _Pragma("unroll")                                                        \
        for (int pr_ = 0; pr_ < 2; pr_++)                                        \
            LDSM4(bf[SET][s_][pr_], (BBASE) + s_ * 16384 + pr_ * 2048 + bk_);    \
    }                                                                            \
} while (0)

// ---------------------------------------------------------------------------
// [3] HOT: bf16x2-split HMMA filter, software-pipelined fragments,
// 4-deep B ring (one barrier per chunk), best-2 + margin test.
// 256 threads, 8 warps (2 M x 4 N), 64 rows x 1024 codes per CTA.
// ---------------------------------------------------------------------------
__global__ void __launch_bounds__(THR, 1)
mma_filter_kernel() {
    extern __shared__ char smem[];
    const uint32_t sb = smem_u32(smem);
    const int tid  = threadIdx.x;
    const int lane = tid & 31;
    const int wid  = tid >> 5;
    const int wx   = wid & 3;        // N warp (32 codes)
    const int wy   = wid >> 2;       // M warp (32 rows), 0..1
    const int row0 = blockIdx.x * ROWS_CTA;

    float* swsq = reinterpret_cast<float*>(smem + SM_WSQ);
    for (int i = tid; i < NC; i += THR) swsq[i] = g_wsq[i];

    // ---- group 0: stage A (full K, 2 splits) + B chunk 0 ----
    {
        const unsigned short* const zs[2] = {g_zh, g_zm};
#pragma unroll
        for (int i = tid; i < 4096; i += THR) {
            int s    = i >> 11;
            int rem  = i & 2047;
            int kc   = rem >> 9;
            int rem2 = rem & 511;
            int r = rem2 >> 3, q = rem2 & 7;
            const unsigned short* src = zs[s] + ((size_t)(row0 + r) * DIM + kc * KC + q * 8);
            uint32_t off = (uint32_t)(r * 128 + ((q * 16) ^ ((r & 7) << 4)));
            CP16(sb + SM_A + s * 32768 + kc * 8192 + off, src);
        }
    }
    stage_B_chunk(sb, tid, 0);
    asm volatile("cp.async.commit_group;" ::: "memory");
    stage_B_chunk(sb, tid, 1);                        // group 1
    asm volatile("cp.async.commit_group;" ::: "memory");

    float Azr[2][2];
#pragma unroll
    for (int mt = 0; mt < 2; mt++)
#pragma unroll
        for (int g = 0; g < 2; g++)
            Azr[mt][g] = g_zsq[row0 + wy * 32 + mt * 16 + (lane >> 2) + g * 8];

    float b1v[2][2], b2v[2][2];
    int   b1i[2][2], b2i[2][2];
#pragma unroll
    for (int mt = 0; mt < 2; mt++)
#pragma unroll
        for (int g = 0; g < 2; g++) {
            b1v[mt][g] = b2v[mt][g] = 3.4e38f;
            b1i[mt][g] = b2i[mt][g] = 0x7fffffff;
        }

    const uint32_t xl   = (uint32_t)((lane & 7) << 4);
    const uint32_t aRow = (uint32_t)((wy * 32 + (lane & 15)) * 128);
    const uint32_t akh  = (uint32_t)(((lane >> 4) & 1) * 16);
    const uint32_t bRow = (uint32_t)((wx * 32 + ((lane >> 4) << 3) + (lane & 7)) * 128);
    const uint32_t bkh  = (uint32_t)(((lane >> 3) & 1) * 16);

    const int pa[3] = {0, 0, 1};
    const int pb[3] = {0, 1, 0};

    // double-buffered fragment registers: set = k16 & 1 (compile-time)
    uint32_t af[2][2][2][4];   // [set][split][mt][4]
    uint32_t bf[2][2][2][4];   // [set][split][pr][4]

    // prologue: B0 valid after wait_group 1 (pending: group1 only)
    asm volatile("cp.async.wait_group 1;" ::: "memory");
    __syncthreads();
    {
        uint32_t ab0 = sb + SM_A + aRow;             // kc=0
        uint32_t bb0 = sb + SM_B + bRow;             // buf 0
        LOADFRAGS(0, ab0, bb0, 0);
    }

    float acc[2][4][4];
#pragma unroll
    for (int mt = 0; mt < 2; mt++)
#pragma unroll
        for (int nt = 0; nt < 4; nt++)
#pragma unroll
            for (int e = 0; e < 4; e++) acc[mt][nt][e] = 0.f;

    for (int it = 0; it < NSTAGE; it++) {
        if (it < NSTAGE - 2) {
            stage_B_chunk(sb, tid, it + 2);
            asm volatile("cp.async.commit_group;" ::: "memory");
            asm volatile("cp.async.wait_group 1;" ::: "memory");
        } else {
            asm volatile("cp.async.wait_group 0;" ::: "memory");
        }
        __syncthreads();   // bufs it and it+1 fully valid for all threads

        const uint32_t ab  = sb + SM_A + (uint32_t)((it & 3) * 8192) + aRow;
        const uint32_t bb  = sb + SM_B + (uint32_t)((it & 3) * 32768) + bRow;
        const uint32_t abn = sb + SM_A + (uint32_t)(((it + 1) & 3) * 8192) + aRow;
        const uint32_t bbn = sb + SM_B + (uint32_t)(((it + 1) & 3) * 32768) + bRow;
        const bool lastit = (it == NSTAGE - 1);

#pragma unroll
        for (int k16 = 0; k16 < 4; k16++) {
            const int cur = k16 & 1;
            const int nxt = cur ^ 1;
            // prefetch next step's frags (hidden under the 24 MMAs below)
            if (k16 < 3) {
                LOADFRAGS(nxt, ab, bb, k16 + 1);
            } else if (!lastit) {
                LOADFRAGS(nxt, abn, bbn, 0);
            }
#pragma unroll
            for (int p = 0; p < 3; p++)
#pragma unroll
                for (int mt = 0; mt < 2; mt++)
#pragma unroll
                    for (int nt = 0; nt < 4; nt++)
                        MMA16816(acc[mt][nt], af[cur][pa[p]][mt],
                                 &bf[cur][pb[p]][nt >> 1][(nt & 1) * 2]);
        }

        if ((it & 3) == 3) {
            // fold this 128-code tile into best-2 (codes ascend per thread)
            const int ct = it >> 2;
#pragma unroll
            for (int nt = 0; nt < 4; nt++) {
                int code0 = ct * 128 + wx * 32 + nt * 8 + (lane & 3) * 2;
                float w0 = swsq[code0], w1 = swsq[code0 + 1];
#pragma unroll
                for (int mt = 0; mt < 2; mt++)
#pragma unroll
                    for (int g = 0; g < 2; g++) {
                        float B0 = acc[mt][nt][g * 2 + 0];
                        float B1 = acc[mt][nt][g * 2 + 1];
                        float d0 = __fadd_rn(__fsub_rn(Azr[mt][g], __fmul_rn(2.f, B0)), w0);
                        float d1 = __fadd_rn(__fsub_rn(Azr[mt][g], __fmul_rn(2.f, B1)), w1);
                        ins2(d0, code0,     b1v[mt][g], b1i[mt][g], b2v[mt][g], b2i[mt][g]);
                        ins2(d1, code0 + 1, b1v[mt][g], b1i[mt][g], b2v[mt][g], b2i[mt][g]);
                    }
            }
#pragma unroll
            for (int mt = 0; mt < 2; mt++)
#pragma unroll
                for (int nt = 0; nt < 4; nt++)
#pragma unroll
                    for (int e = 0; e < 4; e++) acc[mt][nt][e] = 0.f;
        }
    }

    // reduce best-2 across the 4 code-lanes (xor 1,2 stay within lane&3 group)
    float* rv1 = reinterpret_cast<float*>(smem + SM_RED);
    int*   ri1 = reinterpret_cast<int*>(smem + SM_RED + 1024);
    float* rv2 = reinterpret_cast<float*>(smem + SM_RED + 2048);
    int*   ri2 = reinterpret_cast<int*>(smem + SM_RED + 3072);
#pragma unroll
    for (int mt = 0; mt < 2; mt++)
#pragma unroll
        for (int g = 0; g < 2; g++) {
            float v1 = b1v[mt][g], v2 = b2v[mt][g];
            int   i1 = b1i[mt][g], i2 = b2i[mt][g];
#pragma unroll
            for (int m = 1; m <= 2; m <<= 1) {
                float o1v = __shfl_xor_sync(0xffffffffu, v1, m);
                int   o1i = __shfl_xor_sync(0xffffffffu, i1, m);
                float o2v = __shfl_xor_sync(0xffffffffu, v2, m);
                int   o2i = __shfl_xor_sync(0xffffffffu, i2, m);
                ins2(o1v, o1i, v1, i1, v2, i2);
                ins2(o2v, o2i, v1, i1, v2, i2);
            }
            if ((lane & 3) == 0) {
                int rl = wy * 32 + mt * 16 + (lane >> 2) + g * 8;
                rv1[rl * 4 + wx] = v1; ri1[rl * 4 + wx] = i1;
                rv2[rl * 4 + wx] = v2; ri2[rl * 4 + wx] = i2;
            }
        }
    __syncthreads();

    if (tid < ROWS_CTA) {
        float v1 = rv1[tid * 4], v2 = rv2[tid * 4];
        int   i1 = ri1[tid * 4], i2 = ri2[tid * 4];
#pragma unroll
        for (int j = 1; j < 4; j++) {
            ins2(rv1[tid * 4 + j], ri1[tid * 4 + j], v1, i1, v2, i2);
            ins2(rv2[tid * 4 + j], ri2[tid * 4 + j], v1, i1, v2, i2);
        }
        int row = row0 + tid;
        g_idx[row] = i1;
        if (!(v2 - v1 > TAU)) {          // ambiguous -> exact resolve
            int p = atomicAdd(&g_ambig_n, 1);
            g_ambig[p] = row;
        }
    }
}

// ---------------------------------------------------------------------------
// [4] resolver: exact fp32 rescan (proven semantics) of ambiguous rows.
// ---------------------------------------------------------------------------
__global__ void __launch_bounds__(256, 1)
resolve_kernel(const float4* __restrict__ z4, const float4* __restrict__ w4) {
    extern __shared__ float4 sm4[];
    float4* Az = sm4;                    // [RBM][D4]
    float4* Bw = sm4 + RBM * D4;         // [RBN][RKC4] swizzled
    int* rmap  = reinterpret_cast<int*>(sm4 + RBM * D4 + RBN * RKC4);

    const int cnt = g_ambig_n;
    const int bx  = blockIdx.x;
    const int slot0 = (bx >> 1) * RBM;
    if (slot0 >= cnt) return;
    const int half  = bx & 1;
    const int cbase = half * RCHALF;

    const int tid = threadIdx.x;
    const int tx  = tid & 31;
    const int ty  = tid >> 5;

    if (tid < RBM) {
        int s = slot0 + tid;
        rmap[tid] = g_ambig[s < cnt ? s : cnt - 1];
    }
    __syncthreads();

    for (int i = tid; i < RBM * D4; i += 256)
        Az[i] = z4[(size_t)rmap[i >> 6] * D4 + (i & 63)];

    float Ar[RTM];
#pragma unroll
    for (int r = 0; r < RTM; r++) Ar[r] = g_zsq[rmap[ty * RTM + r]];

    float best[RTM];
    int   bidx[RTM];
#pragma unroll
    for (int r = 0; r < RTM; r++) { best[r] = 3.4e38f; bidx[r] = 0x7fffffff; }

    for (int t = 0; t < RNTILE; t++) {
        const int c0 = cbase + t * RBN;

        unsigned long long acc[RTM][RTN];
#pragma unroll
        for (int r = 0; r < RTM; r++)
#pragma unroll
            for (int c = 0; c < RTN; c++) acc[r][c] = 0ull;

        for (int kc4 = 0; kc4 < D4; kc4 += RKC4) {
            __syncthreads();
            for (int i = tid; i < RBN * RKC4; i += 256) {
                int c = i >> 5, q = i & 31;
                Bw[c * RKC4 + (q ^ (c & 31))] = w4[(size_t)(c0 + c) * D4 + kc4 + q];
            }
            __syncthreads();

#pragma unroll 2
            for (int q = 0; q < RKC4; q++) {
                ulonglong2 a[RTM];
#pragma unroll
                for (int r = 0; r < RTM; r++)
                    a[r] = *reinterpret_cast<const ulonglong2*>(
                        &Az[(ty * RTM + r) * D4 + kc4 + q]);
#pragma unroll
                for (int c = 0; c < RTN; c++) {
                    ulonglong2 b = *reinterpret_cast<const ulonglong2*>(
                        &Bw[(c * 32 + tx) * RKC4 + (q ^ tx)]);
#pragma unroll
                    for (int r = 0; r < RTM; r++) {
                        fma2(acc[r][c], a[r].x, b.x);
                        fma2(acc[r][c], a[r].y, b.y);
                    }
                }
            }
        }

#pragma unroll
        for (int c = 0; c < RTN; c++) {
            int code = c0 + c * 32 + tx;
            float wsq = g_wsq[code];
#pragma unroll
            for (int r = 0; r < RTM; r++) {
                float blo, bhi;
                unpack2(acc[r][c], blo, bhi);
                float B = __fadd_rn(blo, bhi);
                float tt = __fsub_rn(Ar[r], __fmul_rn(2.0f, B));
                float d  = __fadd_rn(tt, wsq);
                if (d < best[r]) { best[r] = d; bidx[r] = code; }
            }
        }
    }

#pragma unroll
    for (int r = 0; r < RTM; r++) {
        float v  = best[r];
        int   id = bidx[r];
#pragma unroll
        for (int m = 16; m >= 1; m >>= 1) {
            float ov = __shfl_xor_sync(0xffffffffu, v, m);
            int   oi = __shfl_xor_sync(0xffffffffu, id, m);
            if (ov < v || (ov == v && oi < id)) { v = ov; id = oi; }
        }
        if (tx == 0 && slot0 + ty * RTM + r < cnt) {
            int row = rmap[ty * RTM + r];
            g_best2[half][row] = v;
            g_bidx2[half][row] = id;
        }
    }
}

// ---------------------------------------------------------------------------
// [5] merge resolver halves for ambiguous rows
// ---------------------------------------------------------------------------
__global__ void rmerge_kernel() {
    int i = blockIdx.x * blockDim.x + threadIdx.x;
    if (i >= g_ambig_n) return;
    int row = g_ambig[i];
    float v0 = g_best2[0][row], v1 = g_best2[1][row];
    int   i0 = g_bidx2[0][row], i1 = g_bidx2[1][row];
    g_idx[row] = (v1 < v0 || (v1 == v0 && i1 < i0)) ? i1 : i0;
}

// ---------------------------------------------------------------------------
// [6] gather, [7] index tail
// ---------------------------------------------------------------------------
__global__ void gather_kernel(const float* __restrict__ w, float* __restrict__ out) {
    long gid = (long)blockIdx.x * blockDim.x + threadIdx.x;
    if (gid >= (long)NPTS * D4) return;
    int row = (int)(gid >> 6);
    int col = (int)(gid & 63);
    const float4* w4 = reinterpret_cast<const float4*>(w);
    reinterpret_cast<float4*>(out)[gid] = w4[(size_t)g_idx[row] * D4 + col];
}

__global__ void idx_tail_kernel(float* __restrict__ out, int tail) {
    int i = blockIdx.x * blockDim.x + threadIdx.x;
    if (i >= tail) return;
    out[i] = (i < NPTS) ? (float)g_idx[i] : 0.0f;
}

__global__ void idx_only_kernel(float* __restrict__ out) {
    int i = blockIdx.x * blockDim.x + threadIdx.x;
    if (i < NPTS) out[i] = (float)g_idx[i];
}

// ---------------------------------------------------------------------------
extern "C" void kernel_launch(void* const* d_in, const int* in_sizes, int n_in,
                              void* d_out, int out_size) {
    const float* z = (const float*)d_in[0];
    const float* w = (const float*)d_in[1];

    reset_kernel<<<1, 1>>>();                                    // [0]
    split_w_kernel<<<(NC * 32 + 255) / 256, 256>>>(w);           // [1]
    split_z_kernel<<<(NPTS * 32 + 255) / 256, 256>>>(z);         // [2]

    cudaFuncSetAttribute(mma_filter_kernel,
                         cudaFuncAttributeMaxDynamicSharedMemorySize, SM_TOTAL);
    mma_filter_kernel<<<NPTS / ROWS_CTA, THR, SM_TOTAL>>>();     // [3] HOT

    cudaFuncSetAttribute(resolve_kernel,
                         cudaFuncAttributeMaxDynamicSharedMemorySize, RSM_TOTAL);
    resolve_kernel<<<(NPTS / RBM) * 2, 256, RSM_TOTAL>>>(        // [4]
        reinterpret_cast<const float4*>(z), reinterpret_cast<const float4*>(w));

    rmerge_kernel<<<NPTS / 256, 256>>>();                        // [5]

    const long q_elems = (long)NPTS * DIM;
    if (out_size == NPTS) {
        idx_only_kernel<<<(NPTS + 255) / 256, 256>>>((float*)d_out);
    } else {
        long n4 = q_elems / 4;
        gather_kernel<<<(int)((n4 + 255) / 256), 256>>>(w, (float*)d_out);  // [6]
        long tail = (long)out_size - q_elems;
        if (tail > 0) {
            idx_tail_kernel<<<(int)((tail + 255) / 256), 256>>>(
                (float*)d_out + q_elems, (int)tail);                         // [7]
        }
    }
}

// round 10
// speedup vs baseline: 1.5707x; 1.5707x over previous
#include <cuda_runtime.h>
#include <cuda_fp16.h>
#include <stdint.h>

// Problem constants
#define DIM   256
#define NC    1024
#define NPTS  65536
#define D4    (DIM/4)

// ---- filter kernel geometry ----
#define ROWS_CTA 128
#define NCT      8          // code tiles of 128
#define KC       64
#define THR      512        // 16 warps: wy=wid>>2 (M: 32 rows), wx=wid&3 (N: 32 codes)
#define NSTAGE   32         // NCT * (DIM/KC)
#define TAU      2.5e-4f

// filter smem offsets
#define SM_WSQ   0                     // 4 KB
#define SM_RED   4096                  // 8 KB: rv1,ri1,rv2,ri2 [128][4]
#define SM_A     12288                 // 4 kc x 128 r x 128 B = 64 KB (fp16 z)
#define SM_B     (SM_A + 65536)        // 4 bufs x 128 r x 128 B = 64 KB (fp16 w)
#define SM_TOTAL (SM_B + 65536)        // 143360 B

// ---- resolver geometry (proven-exact fp32 rescan, indirect rows) ----
#define RBM   64
#define RBN   128
#define RKC4  32
#define RTM   8
#define RTN   4
#define RCHALF 512
#define RNTILE (RCHALF/RBN)
#define RSM_TOTAL (65536 + 65536 + 256)

// Scratch (static device globals; no allocation)
__device__ int   g_idx[NPTS];
__device__ float g_wsq[NC];
__device__ float g_zsq[NPTS];
__device__ int   g_ambig_n;
__device__ int   g_ambig[NPTS];
__device__ float g_best2[2][NPTS];
__device__ int   g_bidx2[2][NPTS];
__device__ __align__(16) unsigned short g_zf[NPTS * DIM];   // fp16(z)
__device__ __align__(16) unsigned short g_wf[NC * DIM];     // fp16(w)

// ---- PTX helpers (baseline ops only; no arch-'a' features) -----------------
static __device__ __forceinline__ uint32_t smem_u32(const void* p) {
    uint32_t a;
    asm("{ .reg .u64 t; cvta.to.shared.u64 t, %1; cvt.u32.u64 %0, t; }"
        : "=r"(a) : "l"(p));
    return a;
}
#define CP16(dst, src) \
    asm volatile("cp.async.cg.shared.global [%0], [%1], 16;" :: "r"(dst), "l"(src))
#define LDSM4(r, addr) \
    asm volatile("ldmatrix.sync.aligned.m8n8.x4.shared.b16 {%0,%1,%2,%3}, [%4];" \
                 : "=r"((r)[0]), "=r"((r)[1]), "=r"((r)[2]), "=r"((r)[3]) : "r"(addr))
#define MMA16816F(d, a, b) \
    asm volatile("mma.sync.aligned.m16n8k16.row.col.f32.f16.f16.f32 " \
                 "{%0,%1,%2,%3}, {%4,%5,%6,%7}, {%8,%9}, {%0,%1,%2,%3};" \
                 : "+f"((d)[0]), "+f"((d)[1]), "+f"((d)[2]), "+f"((d)[3]) \
                 : "r"((a)[0]), "r"((a)[1]), "r"((a)[2]), "r"((a)[3]), \
                   "r"((b)[0]), "r"((b)[1]))
static __device__ __forceinline__ void fma2(unsigned long long& d,
                                            unsigned long long a,
                                            unsigned long long b) {
    asm("fma.rn.f32x2 %0, %1, %2, %0;" : "+l"(d) : "l"(a), "l"(b));
}
static __device__ __forceinline__ void unpack2(unsigned long long v,
                                               float& lo, float& hi) {
    asm("mov.b64 {%0, %1}, %2;" : "=f"(lo), "=f"(hi) : "l"(v));
}

// ---------------------------------------------------------------------------
// [0] reset worklist counter
// ---------------------------------------------------------------------------
__global__ void reset_kernel() { g_ambig_n = 0; }

// ---------------------------------------------------------------------------
// [1] convert w -> fp16 + exact fp32 |w|^2. One warp per row, 8 elems/lane.
// ---------------------------------------------------------------------------
__global__ void conv_w_kernel(const float* __restrict__ w) {
    int row  = (blockIdx.x * blockDim.x + threadIdx.x) >> 5;
    int lane = threadIdx.x & 31;
    if (row >= NC) return;
    const float4* src = reinterpret_cast<const float4*>(w + (size_t)row * DIM);
    float4 a = src[lane * 2], b = src[lane * 2 + 1];
    float x[8] = {a.x, a.y, a.z, a.w, b.x, b.y, b.z, b.w};
    float s = 0.f;
    uint32_t pk[4];
#pragma unroll
    for (int j = 0; j < 4; j++) {
        s += x[2 * j] * x[2 * j] + x[2 * j + 1] * x[2 * j + 1];
        uint32_t lo = __half_as_ushort(__float2half_rn(x[2 * j]));
        uint32_t hi = __half_as_ushort(__float2half_rn(x[2 * j + 1]));
        pk[j] = lo | (hi << 16);
    }
    *reinterpret_cast<uint4*>(g_wf + (size_t)row * DIM + lane * 8) =
        make_uint4(pk[0], pk[1], pk[2], pk[3]);
#pragma unroll
    for (int t = 16; t >= 1; t >>= 1) s += __shfl_xor_sync(0xffffffffu, s, t);
    if (lane == 0) g_wsq[row] = s;
}

// ---------------------------------------------------------------------------
// [2] convert z -> fp16 + exact fp32 |z|^2 (fused; z read once)
// ---------------------------------------------------------------------------
__global__ void conv_z_kernel(const float* __restrict__ z) {
    int row  = (blockIdx.x * blockDim.x + threadIdx.x) >> 5;
    int lane = threadIdx.x & 31;
    if (row >= NPTS) return;
    const float4* src = reinterpret_cast<const float4*>(z + (size_t)row * DIM);
    float4 a = src[lane * 2], b = src[lane * 2 + 1];
    float x[8] = {a.x, a.y, a.z, a.w, b.x, b.y, b.z, b.w};
    float s = 0.f;
    uint32_t pk[4];
#pragma unroll
    for (int j = 0; j < 4; j++) {
        s += x[2 * j] * x[2 * j] + x[2 * j + 1] * x[2 * j + 1];
        uint32_t lo = __half_as_ushort(__float2half_rn(x[2 * j]));
        uint32_t hi = __half_as_ushort(__float2half_rn(x[2 * j + 1]));
        pk[j] = lo | (hi << 16);
    }
    *reinterpret_cast<uint4*>(g_zf + (size_t)row * DIM + lane * 8) =
        make_uint4(pk[0], pk[1], pk[2], pk[3]);
#pragma unroll
    for (int t = 16; t >= 1; t >>= 1) s += __shfl_xor_sync(0xffffffffu, s, t);
    if (lane == 0) g_zsq[row] = s;
}

// ---------------------------------------------------------------------------
// B chunk stage into ring buffer (it mod 4): 128 codes x 64 k fp16 (16 KB)
// ---------------------------------------------------------------------------
static __device__ __forceinline__ void stage_B_chunk(uint32_t sb, int tid, int it) {
    const int ct = it >> 2, kc = it & 3, buf = it & 3;
#pragma unroll
    for (int i = tid; i < 1024; i += THR) {
        int r = i >> 3, q = i & 7;
        const unsigned short* src = g_wf + ((size_t)(ct * 128 + r) * DIM + kc * KC + q * 8);
        uint32_t off = (uint32_t)(r * 128 + ((q * 16) ^ ((r & 7) << 4)));
        CP16(sb + SM_B + buf * 16384 + off, src);
    }
}

// lex insert of candidate (v,i) into best-2
static __device__ __forceinline__ void ins2(float v, int i, float& b1v, int& b1i,
                                            float& b2v, int& b2i) {
    if (v < b1v || (v == b1v && i < b1i)) { b2v = b1v; b2i = b1i; b1v = v; b1i = i; }
    else if (v < b2v || (v == b2v && i < b2i)) { b2v = v; b2i = i; }
}

// load one k16 step's fragments into frag set SET
#define LOADFRAGS(SET, ABASE, BBASE, K16) do {                      \
    uint32_t ak_ = ((uint32_t)((K16) * 32) + akh) ^ xl;             \
    uint32_t bk_ = ((uint32_t)((K16) * 32) + bkh) ^ xl;             \
    LDSM4(af[SET][0], (ABASE) + ak_);                               \
    LDSM4(af[SET][1], (ABASE) + 2048 + ak_);                        \
    LDSM4(bf[SET][0], (BBASE) + bk_);                               \
    LDSM4(bf[SET][1], (BBASE) + 2048 + bk_);                        \
} while (0)

// ---------------------------------------------------------------------------
// [3] HOT: single-product fp16 HMMA filter + best-2 + margin test.
// 512 threads, 16 warps (4 M x 4 N), 128 rows x 1024 codes per CTA.
// Error budget: |d_filter - d_ref| noise ~6e-6 rms; TAU=2.5e-4 (~27 sigma)
// certifies decided rows; ambiguous rows go to the exact fp32 resolver.
// ---------------------------------------------------------------------------
__global__ void __launch_bounds__(THR, 1)
mma_filter_kernel() {
    extern __shared__ char smem[];
    const uint32_t sb = smem_u32(smem);
    const int tid  = threadIdx.x;
    const int lane = tid & 31;
    const int wid  = tid >> 5;
    const int wx   = wid & 3;        // N warp (32 codes)
    const int wy   = wid >> 2;       // M warp (32 rows), 0..3
    const int row0 = blockIdx.x * ROWS_CTA;

    float* swsq = reinterpret_cast<float*>(smem + SM_WSQ);
    for (int i = tid; i < NC; i += THR) swsq[i] = g_wsq[i];

    // ---- group 0: stage A (full K) + B chunk 0 ----
#pragma unroll
    for (int i = tid; i < 4096; i += THR) {
        int kc   = i >> 10;
        int rem  = i & 1023;
        int r = rem >> 3, q = rem & 7;
        const unsigned short* src = g_zf + ((size_t)(row0 + r) * DIM + kc * KC + q * 8);
        uint32_t off = (uint32_t)(r * 128 + ((q * 16) ^ ((r & 7) << 4)));
        CP16(sb + SM_A + kc * 16384 + off, src);
    }
    stage_B_chunk(sb, tid, 0);
    asm volatile("cp.async.commit_group;" ::: "memory");
    stage_B_chunk(sb, tid, 1);
    asm volatile("cp.async.commit_group;" ::: "memory");

    float Azr[2][2];
#pragma unroll
    for (int mt = 0; mt < 2; mt++)
#pragma unroll
        for (int g = 0; g < 2; g++)
            Azr[mt][g] = g_zsq[row0 + wy * 32 + mt * 16 + (lane >> 2) + g * 8];

    float b1v[2][2], b2v[2][2];
    int   b1i[2][2], b2i[2][2];
#pragma unroll
    for (int mt = 0; mt < 2; mt++)
#pragma unroll
        for (int g = 0; g < 2; g++) {
            b1v[mt][g] = b2v[mt][g] = 3.4e38f;
            b1i[mt][g] = b2i[mt][g] = 0x7fffffff;
        }

    const uint32_t xl   = (uint32_t)((lane & 7) << 4);
    const uint32_t aRow = (uint32_t)((wy * 32 + (lane & 15)) * 128);
    const uint32_t akh  = (uint32_t)(((lane >> 4) & 1) * 16);
    const uint32_t bRow = (uint32_t)((wx * 32 + ((lane >> 4) << 3) + (lane & 7)) * 128);
    const uint32_t bkh  = (uint32_t)(((lane >> 3) & 1) * 16);

    // double-buffered fragment registers
    uint32_t af[2][2][4];   // [set][mt][4]
    uint32_t bf[2][2][4];   // [set][pr][4]

    // prologue: A + B0 valid after wait_group 1
    asm volatile("cp.async.wait_group 1;" ::: "memory");
    __syncthreads();
    LOADFRAGS(0, sb + SM_A + aRow, sb + SM_B + bRow, 0);

    float acc[2][4][4];
#pragma unroll
    for (int mt = 0; mt < 2; mt++)
#pragma unroll
        for (int nt = 0; nt < 4; nt++)
#pragma unroll
            for (int e = 0; e < 4; e++) acc[mt][nt][e] = 0.f;

    for (int it = 0; it < NSTAGE; it++) {
        if (it < NSTAGE - 2) {
            stage_B_chunk(sb, tid, it + 2);
            asm volatile("cp.async.commit_group;" ::: "memory");
            asm volatile("cp.async.wait_group 1;" ::: "memory");
        } else {
            asm volatile("cp.async.wait_group 0;" ::: "memory");
        }
        __syncthreads();   // bufs it and it+1 fully valid for all threads

        const uint32_t ab  = sb + SM_A + (uint32_t)((it & 3) * 16384) + aRow;
        const uint32_t bb  = sb + SM_B + (uint32_t)((it & 3) * 16384) + bRow;
        const uint32_t abn = sb + SM_A + (uint32_t)(((it + 1) & 3) * 16384) + aRow;
        const uint32_t bbn = sb + SM_B + (uint32_t)(((it + 1) & 3) * 16384) + bRow;
        const bool lastit = (it == NSTAGE - 1);

#pragma unroll
        for (int k16 = 0; k16 < 4; k16++) {
            const int cur = k16 & 1;
            const int nxt = cur ^ 1;
            if (k16 < 3) {
                LOADFRAGS(nxt, ab, bb, k16 + 1);
            } else if (!lastit) {
                LOADFRAGS(nxt, abn, bbn, 0);
            }
#pragma unroll
            for (int mt = 0; mt < 2; mt++)
#pragma unroll
                for (int nt = 0; nt < 4; nt++)
                    MMA16816F(acc[mt][nt], af[cur][mt],
                              &bf[cur][nt >> 1][(nt & 1) * 2]);
        }

        if ((it & 3) == 3) {
            // fold this 128-code tile into best-2 (codes ascend per thread)
            const int ct = it >> 2;
#pragma unroll
            for (int nt = 0; nt < 4; nt++) {
                int code0 = ct * 128 + wx * 32 + nt * 8 + (lane & 3) * 2;
                float w0 = swsq[code0], w1 = swsq[code0 + 1];
#pragma unroll
                for (int mt = 0; mt < 2; mt++)
#pragma unroll
                    for (int g = 0; g < 2; g++) {
                        float B0 = acc[mt][nt][g * 2 + 0];
                        float B1 = acc[mt][nt][g * 2 + 1];
                        float d0 = __fadd_rn(__fsub_rn(Azr[mt][g], __fmul_rn(2.f, B0)), w0);
                        float d1 = __fadd_rn(__fsub_rn(Azr[mt][g], __fmul_rn(2.f, B1)), w1);
                        ins2(d0, code0,     b1v[mt][g], b1i[mt][g], b2v[mt][g], b2i[mt][g]);
                        ins2(d1, code0 + 1, b1v[mt][g], b1i[mt][g], b2v[mt][g], b2i[mt][g]);
                    }
            }
#pragma unroll
            for (int mt = 0; mt < 2; mt++)
#pragma unroll
                for (int nt = 0; nt < 4; nt++)
#pragma unroll
                    for (int e = 0; e < 4; e++) acc[mt][nt][e] = 0.f;
        }
    }

    // reduce best-2 across the 4 code-lanes (xor 1,2 stay within lane&3 group)
    float* rv1 = reinterpret_cast<float*>(smem + SM_RED);
    int*   ri1 = reinterpret_cast<int*>(smem + SM_RED + 2048);
    float* rv2 = reinterpret_cast<float*>(smem + SM_RED + 4096);
    int*   ri2 = reinterpret_cast<int*>(smem + SM_RED + 6144);
#pragma unroll
    for (int mt = 0; mt < 2; mt++)
#pragma unroll
        for (int g = 0; g < 2; g++) {
            float v1 = b1v[mt][g], v2 = b2v[mt][g];
            int   i1 = b1i[mt][g], i2 = b2i[mt][g];
#pragma unroll
            for (int m = 1; m <= 2; m <<= 1) {
                float o1v = __shfl_xor_sync(0xffffffffu, v1, m);
                int   o1i = __shfl_xor_sync(0xffffffffu, i1, m);
                float o2v = __shfl_xor_sync(0xffffffffu, v2, m);
                int   o2i = __shfl_xor_sync(0xffffffffu, i2, m);
                ins2(o1v, o1i, v1, i1, v2, i2);
                ins2(o2v, o2i, v1, i1, v2, i2);
            }
            if ((lane & 3) == 0) {
                int rl = wy * 32 + mt * 16 + (lane >> 2) + g * 8;
                rv1[rl * 4 + wx] = v1; ri1[rl * 4 + wx] = i1;
                rv2[rl * 4 + wx] = v2; ri2[rl * 4 + wx] = i2;
            }
        }
    __syncthreads();

    if (tid < ROWS_CTA) {
        float v1 = rv1[tid * 4], v2 = rv2[tid * 4];
        int   i1 = ri1[tid * 4], i2 = ri2[tid * 4];
#pragma unroll
        for (int j = 1; j < 4; j++) {
            ins2(rv1[tid * 4 + j], ri1[tid * 4 + j], v1, i1, v2, i2);
            ins2(rv2[tid * 4 + j], ri2[tid * 4 + j], v1, i1, v2, i2);
        }
        int row = row0 + tid;
        g_idx[row] = i1;
        if (!(v2 - v1 > TAU)) {          // ambiguous -> exact resolve
            int p = atomicAdd(&g_ambig_n, 1);
            g_ambig[p] = row;
        }
    }
}

// ---------------------------------------------------------------------------
// [4] resolver: exact fp32 rescan (proven semantics) of ambiguous rows.
// ---------------------------------------------------------------------------
__global__ void __launch_bounds__(256, 1)
resolve_kernel(const float4* __restrict__ z4, const float4* __restrict__ w4) {
    extern __shared__ float4 sm4[];
    float4* Az = sm4;                    // [RBM][D4]
    float4* Bw = sm4 + RBM * D4;         // [RBN][RKC4] swizzled
    int* rmap  = reinterpret_cast<int*>(sm4 + RBM * D4 + RBN * RKC4);

    const int cnt = g_ambig_n;
    const int bx  = blockIdx.x;
    const int slot0 = (bx >> 1) * RBM;
    if (slot0 >= cnt) return;
    const int half  = bx & 1;
    const int cbase = half * RCHALF;

    const int tid = threadIdx.x;
    const int tx  = tid & 31;
    const int ty  = tid >> 5;

    if (tid < RBM) {
        int s = slot0 + tid;
        rmap[tid] = g_ambig[s < cnt ? s : cnt - 1];
    }
    __syncthreads();

    for (int i = tid; i < RBM * D4; i += 256)
        Az[i] = z4[(size_t)rmap[i >> 6] * D4 + (i & 63)];

    float Ar[RTM];
#pragma unroll
    for (int r = 0; r < RTM; r++) Ar[r] = g_zsq[rmap[ty * RTM + r]];

    float best[RTM];
    int   bidx[RTM];
#pragma unroll
    for (int r = 0; r < RTM; r++) { best[r] = 3.4e38f; bidx[r] = 0x7fffffff; }

    for (int t = 0; t < RNTILE; t++) {
        const int c0 = cbase + t * RBN;

        unsigned long long acc[RTM][RTN];
#pragma unroll
        for (int r = 0; r < RTM; r++)
#pragma unroll
            for (int c = 0; c < RTN; c++) acc[r][c] = 0ull;

        for (int kc4 = 0; kc4 < D4; kc4 += RKC4) {
            __syncthreads();
            for (int i = tid; i < RBN * RKC4; i += 256) {
                int c = i >> 5, q = i & 31;
                Bw[c * RKC4 + (q ^ (c & 31))] = w4[(size_t)(c0 + c) * D4 + kc4 + q];
            }
            __syncthreads();

#pragma unroll 2
            for (int q = 0; q < RKC4; q++) {
                ulonglong2 a[RTM];
#pragma unroll
                for (int r = 0; r < RTM; r++)
                    a[r] = *reinterpret_cast<const ulonglong2*>(
                        &Az[(ty * RTM + r) * D4 + kc4 + q]);
#pragma unroll
                for (int c = 0; c < RTN; c++) {
                    ulonglong2 b = *reinterpret_cast<const ulonglong2*>(
                        &Bw[(c * 32 + tx) * RKC4 + (q ^ tx)]);
#pragma unroll
                    for (int r = 0; r < RTM; r++) {
                        fma2(acc[r][c], a[r].x, b.x);
                        fma2(acc[r][c], a[r].y, b.y);
                    }
                }
            }
        }

#pragma unroll
        for (int c = 0; c < RTN; c++) {
            int code = c0 + c * 32 + tx;
            float wsq = g_wsq[code];
#pragma unroll
            for (int r = 0; r < RTM; r++) {
                float blo, bhi;
                unpack2(acc[r][c], blo, bhi);
                float B = __fadd_rn(blo, bhi);
                float tt = __fsub_rn(Ar[r], __fmul_rn(2.0f, B));
                float d  = __fadd_rn(tt, wsq);
                if (d < best[r]) { best[r] = d; bidx[r] = code; }
            }
        }
    }

#pragma unroll
    for (int r = 0; r < RTM; r++) {
        float v  = best[r];
        int   id = bidx[r];
#pragma unroll
        for (int m = 16; m >= 1; m >>= 1) {
            float ov = __shfl_xor_sync(0xffffffffu, v, m);
            int   oi = __shfl_xor_sync(0xffffffffu, id, m);
            if (ov < v || (ov == v && oi < id)) { v = ov; id = oi; }
        }
        if (tx == 0 && slot0 + ty * RTM + r < cnt) {
            int row = rmap[ty * RTM + r];
            g_best2[half][row] = v;
            g_bidx2[half][row] = id;
        }
    }
}

// ---------------------------------------------------------------------------
// [5] merge resolver halves for ambiguous rows
// ---------------------------------------------------------------------------
__global__ void rmerge_kernel() {
    int i = blockIdx.x * blockDim.x + threadIdx.x;
    if (i >= g_ambig_n) return;
    int row = g_ambig[i];
    float v0 = g_best2[0][row], v1 = g_best2[1][row];
    int   i0 = g_bidx2[0][row], i1 = g_bidx2[1][row];
    g_idx[row] = (v1 < v0 || (v1 == v0 && i1 < i0)) ? i1 : i0;
}

// ---------------------------------------------------------------------------
// [6] gather, [7] index tail
// ---------------------------------------------------------------------------
__global__ void gather_kernel(const float* __restrict__ w, float* __restrict__ out) {
    long gid = (long)blockIdx.x * blockDim.x + threadIdx.x;
    if (gid >= (long)NPTS * D4) return;
    int row = (int)(gid >> 6);
    int col = (int)(gid & 63);
    const float4* w4 = reinterpret_cast<const float4*>(w);
    reinterpret_cast<float4*>(out)[gid] = w4[(size_t)g_idx[row] * D4 + col];
}

__global__ void idx_tail_kernel(float* __restrict__ out, int tail) {
    int i = blockIdx.x * blockDim.x + threadIdx.x;
    if (i >= tail) return;
    out[i] = (i < NPTS) ? (float)g_idx[i] : 0.0f;
}

__global__ void idx_only_kernel(float* __restrict__ out) {
    int i = blockIdx.x * blockDim.x + threadIdx.x;
    if (i < NPTS) out[i] = (float)g_idx[i];
}

// ---------------------------------------------------------------------------
extern "C" void kernel_launch(void* const* d_in, const int* in_sizes, int n_in,
                              void* d_out, int out_size) {
    const float* z = (const float*)d_in[0];
    const float* w = (const float*)d_in[1];

    reset_kernel<<<1, 1>>>();                                    // [0]
    conv_w_kernel<<<(NC * 32 + 255) / 256, 256>>>(w);            // [1]
    conv_z_kernel<<<(NPTS * 32 + 255) / 256, 256>>>(z);          // [2]

    cudaFuncSetAttribute(mma_filter_kernel,
                         cudaFuncAttributeMaxDynamicSharedMemorySize, SM_TOTAL);
    mma_filter_kernel<<<NPTS / ROWS_CTA, THR, SM_TOTAL>>>();     // [3] HOT

    cudaFuncSetAttribute(resolve_kernel,
                         cudaFuncAttributeMaxDynamicSharedMemorySize, RSM_TOTAL);
    resolve_kernel<<<(NPTS / RBM) * 2, 256, RSM_TOTAL>>>(        // [4]
        reinterpret_cast<const float4*>(z), reinterpret_cast<const float4*>(w));

    rmerge_kernel<<<NPTS / 256, 256>>>();                        // [5]

    const long q_elems = (long)NPTS * DIM;
    if (out_size == NPTS) {
        idx_only_kernel<<<(NPTS + 255) / 256, 256>>>((float*)d_out);
    } else {
        long n4 = q_elems / 4;
        gather_kernel<<<(int)((n4 + 255) / 256), 256>>>(w, (float*)d_out);  // [6]
        long tail = (long)out_size - q_elems;
        if (tail > 0) {
            idx_tail_kernel<<<(int)((tail + 255) / 256), 256>>>(
                (float*)d_out + q_elems, (int)tail);                         // [7]
        }
    }
}